// round 4
// baseline (speedup 1.0000x reference)
#include <cuda_runtime.h>
#include <cstdint>

#define LBL   128
#define NUML  126
#define TSEQ  1024
#define BATCH 256

#define F_LOG2E 1.4426950408889634f
#define F_LN2   0.6931471805599453f

// Precomputed exp-transition matrix (base-2 domain) and per-row log2-max.
__device__ __align__(16) float g_ET[LBL * LBL];
__device__ float g_t2max[LBL];

__device__ __forceinline__ float ex2f_(float x) {
    float y; asm("ex2.approx.ftz.f32 %0, %1;" : "=f"(y) : "f"(x)); return y;
}
__device__ __forceinline__ float lg2f_(float x) {
    float y; asm("lg2.approx.ftz.f32 %0, %1;" : "=f"(y) : "f"(x)); return y;
}
// Packed f32x2 FMA (Blackwell FFMA2): d.lo += a.lo*b.lo ; d.hi += a.hi*b.hi
__device__ __forceinline__ void fma2_(unsigned long long& d,
                                      unsigned long long a,
                                      unsigned long long b) {
    asm("fma.rn.f32x2 %0, %1, %2, %0;" : "+l"(d) : "l"(a), "l"(b));
}
__device__ __forceinline__ unsigned long long add2_(unsigned long long a,
                                                    unsigned long long b) {
    unsigned long long d;
    asm("add.rn.f32x2 %0, %1, %2;" : "=l"(d) : "l"(a), "l"(b));
    return d;
}

// ---------------------------------------------------------------------------
// prep: ET[y][x] = exp2( T2[y,x] - t2max[y] ), all in base-2 domain.
// ---------------------------------------------------------------------------
__global__ void crf_prep_kernel(const float* __restrict__ T) {
    int y = blockIdx.x;
    int x = threadIdx.x;
    __shared__ float s[LBL];
    float v = T[y * LBL + x];
    s[x] = v;
    __syncthreads();
    #pragma unroll
    for (int o = 64; o; o >>= 1) {
        if (x < o) s[x] = fmaxf(s[x], s[x + o]);
        __syncthreads();
    }
    float t2m = s[0] * F_LOG2E;               // log2-domain row max
    g_ET[y * LBL + x] = ex2f_(v * F_LOG2E - t2m);
    if (x == 0) g_t2max[y] = t2m;
}

// ---------------------------------------------------------------------------
// main: one CTA per sequence. Thread y owns state y; ET row y in registers.
// Linear-domain forward recursion; scale anchored on W[0]'s float exponent.
//   invariant: true_alpha2[y] at step t == lg2(W[y]) + Ci   (+ per-row t2m
//   telescoping handled inside el), Ci exact integer bookkeeping.
// ---------------------------------------------------------------------------
__global__ __launch_bounds__(128, 2) void crf_main_kernel(
    const float* __restrict__ logits,   // [B, T, NUML] f32
    const int*   __restrict__ labels,   // [B, T]
    const int*   __restrict__ lens,     // [B]
    const float* __restrict__ T,        // [L, L]
    float*       __restrict__ out)      // [B]
{
    const int b = blockIdx.x;
    const int y = threadIdx.x;
    const int len = lens[b];
    const int*   lab = labels + b * TSEQ;
    const float* lg  = logits + (size_t)b * TSEQ * NUML;

    __shared__ __align__(16) float s_v[2][LBL];   // double-buffered W
    __shared__ float s_red[4];

    // -------- gold score (unary + binary along the label path) --------
    float gold = 0.f;
    for (int t = y; t < len; t += 128) {
        int l = lab[t];
        gold += lg[(size_t)t * NUML + l];             // unary
        int from = (t == 0) ? (LBL - 2) : lab[t - 1]; // binary hop t
        gold += T[l * LBL + from];
    }
    if (y == 0) {                                     // final hop: last -> end
        int from = lab[len - 1];
        gold += T[(LBL - 1) * LBL + from];
    }
    #pragma unroll
    for (int o = 16; o; o >>= 1) gold += __shfl_xor_sync(0xffffffffu, gold, o);
    if ((y & 31) == 0) s_red[y >> 5] = gold;
    __syncthreads();
    gold = s_red[0] + s_red[1] + s_red[2] + s_red[3];

    // -------- ET row y into 64 packed f32x2 registers --------
    unsigned long long et2[64];
    {
        const ulonglong2* p =
            reinterpret_cast<const ulonglong2*>(&g_ET[y * LBL]);
        #pragma unroll
        for (int k = 0; k < 32; k++) {
            ulonglong2 q = p[k];
            et2[2 * k]     = q.x;
            et2[2 * k + 1] = q.y;
        }
    }
    const float t2m   = g_t2max[y];
    const float tend2 = T[(LBL - 1) * LBL + y] * F_LOG2E;

    // W_0: start state = 1, everything else = 0 (true value exp(-100): below
    // f32 LSE resolution, exactly as in the reference's own arithmetic).
    float W = (y == LBL - 2) ? 1.f : 0.f;
    s_v[0][y] = W;
    int Ci = 0;                                // accumulated log2 rescales

    // ---- logit prefetch pipeline, distance 3, pointer-bumped addressing ----
    // Values loaded past len-1 are never consumed (they'd reach l0 only at
    // t >= len); addresses are clamped to len-1 so they stay in-bounds.
    const bool live = (y < NUML);
    const float PADL = -1000.f * F_LOG2E;
    const float* lp = lg + y;                  // row t=0
    const int last = len - 1;
    float l0, l1, l2;
    {
        int t1 = (1 < len) ? 1 : last;
        int t2 = (2 < len) ? 2 : last;
        l0 = live ? __ldg(lp) * F_LOG2E : PADL;
        l1 = live ? __ldg(lp + (size_t)t1 * NUML) * F_LOG2E : PADL;
        l2 = live ? __ldg(lp + (size_t)t2 * NUML) * F_LOG2E : PADL;
        lp += (size_t)((3 < len) ? 3 : last) * NUML;   // row min(3,last)
    }

    for (int t = 0; t < len; ++t) {
        const int cur = t & 1;
        __syncthreads();    // publishes s_v[cur] (single barrier per step)

        // uniform power-of-2 rescale from the anchor state's exponent
        float w0 = s_v[cur][0];
        int e = ((__float_as_int(w0) >> 23) & 0xff) - 127;
        e = (t == 0) ? 0 : e;                  // W_0[0] == 0; anchor is start
        float r = __int_as_float((127 - e) << 23);   // exact 2^(-e)
        Ci += e;

        // per-state logit factor (off the critical path)
        float el = ex2f_(l0 + t2m);

        // prefetch logit for step t+3 (clamped address, value maybe unused)
        float l3v = live ? __ldg(lp) * F_LOG2E : PADL;
        lp += (t + 4 < len) ? NUML : 0;

        // dot(ET[y,:], W[:]) with packed f32x2, 4 independent accumulators
        unsigned long long ac0 = 0ull, ac1 = 0ull, ac2 = 0ull, ac3 = 0ull;
        const ulonglong2* vp = reinterpret_cast<const ulonglong2*>(s_v[cur]);
        #pragma unroll
        for (int k = 0; k < 16; k++) {
            ulonglong2 va = vp[2 * k];
            ulonglong2 vb = vp[2 * k + 1];
            fma2_(ac0, et2[4 * k + 0], va.x);
            fma2_(ac1, et2[4 * k + 1], va.y);
            fma2_(ac2, et2[4 * k + 2], vb.x);
            fma2_(ac3, et2[4 * k + 3], vb.y);
        }
        unsigned long long sA = add2_(add2_(ac0, ac1), add2_(ac2, ac3));
        float accl = __int_as_float((int)(unsigned)(sA & 0xffffffffull));
        float acch = __int_as_float((int)(unsigned)(sA >> 32));
        float acc  = accl + acch;

        W = el * (acc * r);
        s_v[cur ^ 1][y] = W;                   // write next buffer
        l0 = l1; l1 = l2; l2 = l3v;
    }

    // -------- final norm: LSE over lg2(W) + Ci + T2[end, :] --------
    float f = lg2f_(W) + tend2;                // -inf for dead states: safe
    float fm = f;
    #pragma unroll
    for (int o = 16; o; o >>= 1)
        fm = fmaxf(fm, __shfl_xor_sync(0xffffffffu, fm, o));
    if ((y & 31) == 0) s_red[y >> 5] = fm;
    __syncthreads();
    fm = fmaxf(fmaxf(s_red[0], s_red[1]), fmaxf(s_red[2], s_red[3]));
    __syncthreads();

    float ee = ex2f_(f - fm);
    #pragma unroll
    for (int o = 16; o; o >>= 1) ee += __shfl_xor_sync(0xffffffffu, ee, o);
    if ((y & 31) == 0) s_red[y >> 5] = ee;
    __syncthreads();
    float S = s_red[0] + s_red[1] + s_red[2] + s_red[3];

    float norm = ((float)Ci + fm + lg2f_(S)) * F_LN2;
    if (y == 0) out[b] = gold - norm;
}

// ---------------------------------------------------------------------------
extern "C" void kernel_launch(void* const* d_in, const int* in_sizes, int n_in,
                              void* d_out, int out_size) {
    const float* logits = (const float*)d_in[0];
    const int*   labels = (const int*)d_in[1];
    const int*   lens   = (const int*)d_in[2];
    const float* T      = (const float*)d_in[3];
    float* out = (float*)d_out;

    crf_prep_kernel<<<LBL, LBL>>>(T);
    crf_main_kernel<<<BATCH, LBL>>>(logits, labels, lens, T, out);
}